// round 1
// baseline (speedup 1.0000x reference)
#include <cuda_runtime.h>
#include <cuda_bf16.h>

// Conv2d: x[32,128,56,56] (NCHW f32) * w[256,128,3,3] (OIHW f32) -> out[32,256,56,56]
// stride 1, pad 1, no bias.
//
// Baseline round: fp32 SIMT direct conv, implicit-GEMM tiling.
// Block: 128 oc x (14w x 8h) pixels of one image. 256 threads, each 8 oc x 7 px.

#define CT 8              // input channels staged per k-chunk
#define XS_STRIDE 17      // padded row stride (16 cols of halo'd tile)
#define XS_PLANE  (10 * XS_STRIDE)   // 10 halo rows
#define WS_K      (CT * 9)
#define WS_STRIDE 129     // 128 oc padded by 1 to kill store conflicts

__global__ __launch_bounds__(256, 2)
void conv3x3_f32_kernel(const float* __restrict__ x,
                        const float* __restrict__ w,
                        float* __restrict__ out) {
    __shared__ float xs[CT * XS_PLANE];        // 1360 f  (5.4 KB)
    __shared__ float ws[WS_K * WS_STRIDE];     // 9288 f (37.2 KB)

    const int tid = threadIdx.x;
    const int bx  = blockIdx.x;                // 0..27 spatial tile
    const int ocb = blockIdx.y << 7;           // 0 or 128
    const int n   = blockIdx.z;                // image

    const int tx = bx & 3;                     // col tile 0..3  (14 wide)
    const int ty = bx >> 2;                    // row tile 0..6  (8 high)
    const int c0 = tx * 14;
    const int r0 = ty * 8;

    const int toc = tid >> 4;                  // 0..15 -> 8 oc each
    const int tpx = tid & 15;                  // 0..15 -> 7 px each

    // Per-thread pixel offsets inside the padded smem plane.
    int p[7];
    #pragma unroll
    for (int j = 0; j < 7; j++) {
        int px  = tpx * 7 + j;                 // 0..111
        int row = px / 14;
        int col = px - row * 14;
        p[j] = row * XS_STRIDE + col;
    }

    float acc[8][7];
    #pragma unroll
    for (int i = 0; i < 8; i++)
        #pragma unroll
        for (int j = 0; j < 7; j++)
            acc[i][j] = 0.0f;

    const float* xn = x + (size_t)n * 128 * 56 * 56;

    for (int cc = 0; cc < 128; cc += CT) {
        // ---- stage input patch: CT x 10 x 16 (zero-padded halo) ----
        for (int e = tid; e < CT * 160; e += 256) {
            int ch   = e / 160;
            int rem  = e - ch * 160;
            int rr   = rem >> 4;
            int ccol = rem & 15;
            int gr   = r0 - 1 + rr;
            int gc   = c0 - 1 + ccol;
            float v = 0.0f;
            if ((unsigned)gr < 56u && (unsigned)gc < 56u)
                v = xn[((cc + ch) * 56 + gr) * 56 + gc];
            xs[ch * XS_PLANE + rr * XS_STRIDE + ccol] = v;
        }
        // ---- stage weights: k-major ws[k][oc], k = ct*9 + kh*3 + kw ----
        {
            const float* wp = w + (size_t)ocb * 1152 + cc * 9;
            for (int e = tid; e < 128 * WS_K; e += 256) {
                int oc_l = e / WS_K;
                int k    = e - oc_l * WS_K;
                ws[k * WS_STRIDE + oc_l] = wp[oc_l * 1152 + k];
            }
        }
        __syncthreads();

        // ---- compute: 72 k-steps per chunk ----
        #pragma unroll 1
        for (int ct = 0; ct < CT; ct++) {
            const float* xplane = xs + ct * XS_PLANE;
            const float* wbase  = ws + (ct * 9) * WS_STRIDE + (toc << 3);
            #pragma unroll
            for (int kh = 0; kh < 3; kh++) {
                #pragma unroll
                for (int kw = 0; kw < 3; kw++) {
                    const float* wk = wbase + (kh * 3 + kw) * WS_STRIDE;
                    float wf[8];
                    #pragma unroll
                    for (int i = 0; i < 8; i++)
                        wf[i] = wk[i];
                    const float* xp = xplane + kh * XS_STRIDE + kw;
                    float xf[7];
                    #pragma unroll
                    for (int j = 0; j < 7; j++)
                        xf[j] = xp[p[j]];
                    #pragma unroll
                    for (int i = 0; i < 8; i++)
                        #pragma unroll
                        for (int j = 0; j < 7; j++)
                            acc[i][j] = fmaf(wf[i], xf[j], acc[i][j]);
                }
            }
        }
        __syncthreads();
    }

    // ---- writeback (no guards: 14|56 and 8|56) ----
    float* on = out + ((size_t)n * 256 + ocb + (toc << 3)) * 3136;
    #pragma unroll
    for (int i = 0; i < 8; i++) {
        float* op = on + (size_t)i * 3136;
        #pragma unroll
        for (int j = 0; j < 7; j++) {
            int px  = tpx * 7 + j;
            int row = px / 14;
            int col = px - row * 14;
            op[(r0 + row) * 56 + (c0 + col)] = acc[i][j];
        }
    }
}

extern "C" void kernel_launch(void* const* d_in, const int* in_sizes, int n_in,
                              void* d_out, int out_size) {
    const float* x = (const float*)d_in[0];   // [32,128,56,56]
    const float* w = (const float*)d_in[1];   // [256,128,3,3]
    float* out = (float*)d_out;               // [32,256,56,56]

    dim3 grid(28, 2, 32);   // spatial tiles, oc tiles, images
    dim3 block(256);
    conv3x3_f32_kernel<<<grid, block>>>(x, w, out);
}

// round 2
// speedup vs baseline: 1.0546x; 1.0546x over previous
#include <cuda_runtime.h>
#include <cuda_bf16.h>

// Conv2d: x[32,128,56,56] (NCHW f32) * w[256,128,3,3] (OIHW f32) -> out[32,256,56,56]
// stride 1, pad 1, no bias.
//
// Baseline round: fp32 SIMT direct conv, implicit-GEMM tiling.
// Block: 128 oc x (14w x 8h) pixels of one image. 256 threads, each 8 oc x 7 px.

#define CT 8              // input channels staged per k-chunk
#define XS_STRIDE 17      // padded row stride (16 cols of halo'd tile)
#define XS_PLANE  (10 * XS_STRIDE)   // 10 halo rows
#define WS_K      (CT * 9)
#define WS_STRIDE 129     // 128 oc padded by 1 to kill store conflicts

__global__ __launch_bounds__(256, 2)
void conv3x3_f32_kernel(const float* __restrict__ x,
                        const float* __restrict__ w,
                        float* __restrict__ out) {
    __shared__ float xs[CT * XS_PLANE];        // 1360 f  (5.4 KB)
    __shared__ float ws[WS_K * WS_STRIDE];     // 9288 f (37.2 KB)

    const int tid = threadIdx.x;
    const int bx  = blockIdx.x;                // 0..27 spatial tile
    const int ocb = blockIdx.y << 7;           // 0 or 128
    const int n   = blockIdx.z;                // image

    const int tx = bx & 3;                     // col tile 0..3  (14 wide)
    const int ty = bx >> 2;                    // row tile 0..6  (8 high)
    const int c0 = tx * 14;
    const int r0 = ty * 8;

    const int toc = tid >> 4;                  // 0..15 -> 8 oc each
    const int tpx = tid & 15;                  // 0..15 -> 7 px each

    // Per-thread pixel offsets inside the padded smem plane.
    int p[7];
    #pragma unroll
    for (int j = 0; j < 7; j++) {
        int px  = tpx * 7 + j;                 // 0..111
        int row = px / 14;
        int col = px - row * 14;
        p[j] = row * XS_STRIDE + col;
    }

    float acc[8][7];
    #pragma unroll
    for (int i = 0; i < 8; i++)
        #pragma unroll
        for (int j = 0; j < 7; j++)
            acc[i][j] = 0.0f;

    const float* xn = x + (size_t)n * 128 * 56 * 56;

    for (int cc = 0; cc < 128; cc += CT) {
        // ---- stage input patch: CT x 10 x 16 (zero-padded halo) ----
        for (int e = tid; e < CT * 160; e += 256) {
            int ch   = e / 160;
            int rem  = e - ch * 160;
            int rr   = rem >> 4;
            int ccol = rem & 15;
            int gr   = r0 - 1 + rr;
            int gc   = c0 - 1 + ccol;
            float v = 0.0f;
            if ((unsigned)gr < 56u && (unsigned)gc < 56u)
                v = xn[((cc + ch) * 56 + gr) * 56 + gc];
            xs[ch * XS_PLANE + rr * XS_STRIDE + ccol] = v;
        }
        // ---- stage weights: k-major ws[k][oc], k = ct*9 + kh*3 + kw ----
        {
            const float* wp = w + (size_t)ocb * 1152 + cc * 9;
            for (int e = tid; e < 128 * WS_K; e += 256) {
                int oc_l = e / WS_K;
                int k    = e - oc_l * WS_K;
                ws[k * WS_STRIDE + oc_l] = wp[oc_l * 1152 + k];
            }
        }
        __syncthreads();

        // ---- compute: 72 k-steps per chunk ----
        #pragma unroll 1
        for (int ct = 0; ct < CT; ct++) {
            const float* xplane = xs + ct * XS_PLANE;
            const float* wbase  = ws + (ct * 9) * WS_STRIDE + (toc << 3);
            #pragma unroll
            for (int kh = 0; kh < 3; kh++) {
                #pragma unroll
                for (int kw = 0; kw < 3; kw++) {
                    const float* wk = wbase + (kh * 3 + kw) * WS_STRIDE;
                    float wf[8];
                    #pragma unroll
                    for (int i = 0; i < 8; i++)
                        wf[i] = wk[i];
                    const float* xp = xplane + kh * XS_STRIDE + kw;
                    float xf[7];
                    #pragma unroll
                    for (int j = 0; j < 7; j++)
                        xf[j] = xp[p[j]];
                    #pragma unroll
                    for (int i = 0; i < 8; i++)
                        #pragma unroll
                        for (int j = 0; j < 7; j++)
                            acc[i][j] = fmaf(wf[i], xf[j], acc[i][j]);
                }
            }
        }
        __syncthreads();
    }

    // ---- writeback (no guards: 14|56 and 8|56) ----
    float* on = out + ((size_t)n * 256 + ocb + (toc << 3)) * 3136;
    #pragma unroll
    for (int i = 0; i < 8; i++) {
        float* op = on + (size_t)i * 3136;
        #pragma unroll
        for (int j = 0; j < 7; j++) {
            int px  = tpx * 7 + j;
            int row = px / 14;
            int col = px - row * 14;
            op[(r0 + row) * 56 + (c0 + col)] = acc[i][j];
        }
    }
}

extern "C" void kernel_launch(void* const* d_in, const int* in_sizes, int n_in,
                              void* d_out, int out_size) {
    const float* x = (const float*)d_in[0];   // [32,128,56,56]
    const float* w = (const float*)d_in[1];   // [256,128,3,3]
    float* out = (float*)d_out;               // [32,256,56,56]

    dim3 grid(28, 2, 32);   // spatial tiles, oc tiles, images
    dim3 block(256);
    conv3x3_f32_kernel<<<grid, block>>>(x, w, out);
}

// round 4
// speedup vs baseline: 3.0001x; 2.8448x over previous
#include <cuda_runtime.h>
#include <cstdint>

// Conv2d 3x3: x[32,128,56,56] f32 * w[256,128,3,3] f32 -> out[32,256,56,56]
// tf32 mma.sync (HMMA) implicit GEMM. CTA: M=128 oc x N=128 flat pixels, K=1152 in 72 k16 chunks.
// Double-buffered smem, 80B-padded rows (conflict-free ldmatrix), im2col via smem offset table.

static __device__ __forceinline__ uint32_t smem_u32(const void* p) {
    uint32_t a;
    asm("{ .reg .u64 t; cvta.to.shared.u64 t, %1; cvt.u32.u64 %0, t; }" : "=r"(a) : "l"(p));
    return a;
}
static __device__ __forceinline__ uint32_t totf(float f) {
    float r; asm("cvt.rna.tf32.f32 %0, %1;" : "=f"(r) : "f"(f));
    return __float_as_uint(r);
}

#define LDSM4(r, addr) \
    asm volatile("ldmatrix.sync.aligned.m8n8.x4.shared.b16 {%0,%1,%2,%3}, [%4];" \
        : "=r"((r)[0]), "=r"((r)[1]), "=r"((r)[2]), "=r"((r)[3]) : "r"(addr))

#define MMA1688(d, a, b0, b1) \
    asm volatile("mma.sync.aligned.m16n8k8.row.col.f32.tf32.tf32.f32 " \
        "{%0,%1,%2,%3}, {%4,%5,%6,%7}, {%8,%9}, {%0,%1,%2,%3};" \
        : "+f"((d)[0]), "+f"((d)[1]), "+f"((d)[2]), "+f"((d)[3]) \
        : "r"((a)[0]), "r"((a)[1]), "r"((a)[2]), "r"((a)[3]), "r"(b0), "r"(b1))

#define STS4(addr, v0, v1, v2, v3) \
    asm volatile("st.shared.v4.b32 [%0], {%1,%2,%3,%4};" \
        :: "r"(addr), "r"(v0), "r"(v1), "r"(v2), "r"(v3) : "memory")

#define ROWB 80u            // padded smem row stride in bytes (20 floats)
#define TILEB (128u * ROWB) // 10240 bytes per operand tile

__global__ void __launch_bounds__(256, 2)
conv3x3_tf32_hmma(const float* __restrict__ x, const float* __restrict__ w,
                  float* __restrict__ out)
{
    __shared__ int   s_tbl[1152];
    __shared__ float s_A[2][2560];   // 2 x 128 rows x 20 floats
    __shared__ float s_B[2][2560];

    const int tid  = threadIdx.x;
    const int lane = tid & 31;
    const int wid  = tid >> 5;
    const int warpM = wid & 3;        // 0..3 -> 32 oc each
    const int warpN = wid >> 2;       // 0..1 -> 64 px each

    const int bx  = blockIdx.x;       // 0..783 flat pixel tile
    const int ocb = blockIdx.y << 7;  // 0 / 128
    const int gp0 = bx << 7;

    // ---- k -> (plane offset, r9) table ----
    for (int k = tid; k < 1152; k += 256) {
        int ic = k / 9;
        int r9 = k - ic * 9;
        int kh = r9 / 3;
        int kw = r9 - kh * 3;
        int off = ic * 3136 + (kh - 1) * 56 + (kw - 1);
        s_tbl[k] = (off << 4) | r9;
    }

    // ---- per-thread staging geometry ----
    const int spx = tid >> 1;         // pixel row of B tile / oc row of A tile
    const int skh = tid & 1;          // which k-octet of the 16-k chunk
    const int gp  = gp0 + spx;
    const int img = gp / 3136;
    const int p   = gp - img * 3136;
    const int r   = p / 56;
    const int c   = p - r * 56;
    unsigned mask9 = 0;
    #pragma unroll
    for (int dh = -1; dh <= 1; dh++)
        #pragma unroll
        for (int dw = -1; dw <= 1; dw++)
            if ((unsigned)(r + dh) < 56u && (unsigned)(c + dw) < 56u)
                mask9 |= 1u << ((dh + 1) * 3 + (dw + 1));
    const float* pbase = x + (size_t)img * 401408 + p;
    const float* wsrc  = w + (size_t)(ocb + spx) * 1152 + skh * 8;
    const uint32_t sts_off = (uint32_t)spx * ROWB + (uint32_t)skh * 32u;

    const uint32_t aS = smem_u32(s_A[0]);
    const uint32_t bS = smem_u32(s_B[0]);

    // ldmatrix per-lane base offsets
    const uint32_t aoff = (uint32_t)(warpM * 32 + (lane & 15)) * ROWB + (uint32_t)((lane >> 4) << 4);
    const uint32_t boff = (uint32_t)(warpN * 64 + (lane & 7) + ((lane >> 4) << 3)) * ROWB
                        + (uint32_t)(((lane >> 3) & 1) << 4);

    float acc[2][8][4];
    #pragma unroll
    for (int i = 0; i < 2; i++)
        #pragma unroll
        for (int j = 0; j < 8; j++)
            #pragma unroll
            for (int q = 0; q < 4; q++) acc[i][j][q] = 0.0f;

    __syncthreads();   // tbl ready

    // ---- prologue: stage chunk 0 into buffer 0 ----
    {
        float4 wa = *reinterpret_cast<const float4*>(wsrc);
        float4 wb = *reinterpret_cast<const float4*>(wsrc + 4);
        int4 e0 = *reinterpret_cast<const int4*>(&s_tbl[skh * 8]);
        int4 e1 = *reinterpret_cast<const int4*>(&s_tbl[skh * 8 + 4]);
        float bv[8];
        int ee[8] = {e0.x, e0.y, e0.z, e0.w, e1.x, e1.y, e1.z, e1.w};
        #pragma unroll
        for (int j = 0; j < 8; j++) {
            int en = ee[j];
            bool ok = (mask9 >> (en & 15)) & 1u;
            float v = 0.0f;
            if (ok) v = __ldg(pbase + (en >> 4));
            bv[j] = v;
        }
        STS4(aS + sts_off,       totf(wa.x), totf(wa.y), totf(wa.z), totf(wa.w));
        STS4(aS + sts_off + 16,  totf(wb.x), totf(wb.y), totf(wb.z), totf(wb.w));
        STS4(bS + sts_off,       totf(bv[0]), totf(bv[1]), totf(bv[2]), totf(bv[3]));
        STS4(bS + sts_off + 16,  totf(bv[4]), totf(bv[5]), totf(bv[6]), totf(bv[7]));
    }
    __syncthreads();

    for (int ch = 0; ch < 72; ch++) {
        const int cur = ch & 1;

        // ---- issue gmem loads for next chunk ----
        float4 wa, wb;
        float bv[8];
        if (ch < 71) {
            const int kb = (ch + 1) * 16 + skh * 8;
            wa = *reinterpret_cast<const float4*>(wsrc + (ch + 1) * 16);
            wb = *reinterpret_cast<const float4*>(wsrc + (ch + 1) * 16 + 4);
            int4 e0 = *reinterpret_cast<const int4*>(&s_tbl[kb]);
            int4 e1 = *reinterpret_cast<const int4*>(&s_tbl[kb + 4]);
            int ee[8] = {e0.x, e0.y, e0.z, e0.w, e1.x, e1.y, e1.z, e1.w};
            #pragma unroll
            for (int j = 0; j < 8; j++) {
                int en = ee[j];
                bool ok = (mask9 >> (en & 15)) & 1u;
                float v = 0.0f;
                if (ok) v = __ldg(pbase + (en >> 4));
                bv[j] = v;
            }
        }

        // ---- compute on current buffer: 2 k8 steps ----
        const uint32_t aBuf = aS + (uint32_t)cur * TILEB;
        const uint32_t bBuf = bS + (uint32_t)cur * TILEB;
        #pragma unroll
        for (int s = 0; s < 2; s++) {
            uint32_t af[2][4];
            #pragma unroll
            for (int i = 0; i < 2; i++)
                LDSM4(af[i], aBuf + aoff + (uint32_t)(i * 16) * ROWB + (uint32_t)(s * 32));
            uint32_t bf[4][4];
            #pragma unroll
            for (int jj = 0; jj < 4; jj++)
                LDSM4(bf[jj], bBuf + boff + (uint32_t)(jj * 16) * ROWB + (uint32_t)(s * 32));
            #pragma unroll
            for (int i = 0; i < 2; i++)
                #pragma unroll
                for (int j = 0; j < 8; j++)
                    MMA1688(acc[i][j], af[i], bf[j >> 1][(j & 1) * 2], bf[j >> 1][(j & 1) * 2 + 1]);
        }

        // ---- store staged regs into the other buffer ----
        if (ch < 71) {
            const uint32_t aN = aS + (uint32_t)(cur ^ 1) * TILEB + sts_off;
            const uint32_t bN = bS + (uint32_t)(cur ^ 1) * TILEB + sts_off;
            STS4(aN,      totf(wa.x), totf(wa.y), totf(wa.z), totf(wa.w));
            STS4(aN + 16, totf(wb.x), totf(wb.y), totf(wb.z), totf(wb.w));
            STS4(bN,      totf(bv[0]), totf(bv[1]), totf(bv[2]), totf(bv[3]));
            STS4(bN + 16, totf(bv[4]), totf(bv[5]), totf(bv[6]), totf(bv[7]));
        }
        __syncthreads();
    }

    // ---- epilogue: direct STG.64 per fragment pair ----
    #pragma unroll
    for (int i = 0; i < 2; i++) {
        const int mrow = ocb + warpM * 32 + i * 16 + (lane >> 2);
        #pragma unroll
        for (int j = 0; j < 8; j++) {
            int nl  = warpN * 64 + j * 8 + 2 * (lane & 3);
            int gp2 = gp0 + nl;
            int im2 = gp2 / 3136;
            int pp  = gp2 - im2 * 3136;
            float* o0 = out + ((size_t)im2 * 256 + mrow) * 3136 + pp;
            float2 v0 = make_float2(acc[i][j][0], acc[i][j][1]);
            float2 v1 = make_float2(acc[i][j][2], acc[i][j][3]);
            *reinterpret_cast<float2*>(o0)             = v0;
            *reinterpret_cast<float2*>(o0 + 8 * 3136)  = v1;
        }
    }
}

extern "C" void kernel_launch(void* const* d_in, const int* in_sizes, int n_in,
                              void* d_out, int out_size) {
    const float* x = (const float*)d_in[0];   // [32,128,56,56]
    const float* w = (const float*)d_in[1];   // [256,128,3,3]
    float* out = (float*)d_out;               // [32,256,56,56]

    dim3 grid(784, 2);   // flat 128-pixel tiles, oc halves
    conv3x3_tf32_hmma<<<grid, 256>>>(x, w, out);
}

// round 5
// speedup vs baseline: 3.7893x; 1.2630x over previous
#include <cuda_runtime.h>
#include <cstdint>

// Conv2d 3x3: x[32,128,56,56] f32 * w[256,128,3,3] f32 -> out[32,256,56,56]
// tf32 mma.sync implicit GEMM. CTA: M=256 oc x N=64 flat px, K=1152 (72 k16 chunks).
// A fragments pre-packed to gmem (prep kernel) -> direct LDG.128, no smem for A.
// B im2col staged to smem (double buffer, 80B rows), ldmatrix consumed.

static __device__ __forceinline__ uint32_t smem_u32(const void* p) {
    uint32_t a;
    asm("{ .reg .u64 t; cvta.to.shared.u64 t, %1; cvt.u32.u64 %0, t; }" : "=r"(a) : "l"(p));
    return a;
}
static __device__ __forceinline__ uint32_t totf(float f) {
    float r; asm("cvt.rna.tf32.f32 %0, %1;" : "=f"(r) : "f"(f));
    return __float_as_uint(r);
}

#define LDSM4(r, addr) \
    asm volatile("ldmatrix.sync.aligned.m8n8.x4.shared.b16 {%0,%1,%2,%3}, [%4];" \
        : "=r"((r)[0]), "=r"((r)[1]), "=r"((r)[2]), "=r"((r)[3]) : "r"(addr))

#define MMA1688(d, a, b0, b1) \
    asm volatile("mma.sync.aligned.m16n8k8.row.col.f32.tf32.tf32.f32 " \
        "{%0,%1,%2,%3}, {%4,%5,%6,%7}, {%8,%9}, {%0,%1,%2,%3};" \
        : "+f"((d)[0]), "+f"((d)[1]), "+f"((d)[2]), "+f"((d)[3]) \
        : "r"((a)[0]), "r"((a)[1]), "r"((a)[2]), "r"((a)[3]), "r"(b0), "r"(b1))

#define STS4(addr, v0, v1, v2, v3) \
    asm volatile("st.shared.v4.b32 [%0], {%1,%2,%3,%4};" \
        :: "r"(addr), "r"(v0), "r"(v1), "r"(v2), "r"(v3) : "memory")

#define ROWB 80u              // B smem row stride (16 k * 4B data + pad)
#define BTILE (64u * ROWB)    // 5120 B per buffer

// Pre-packed A: [kb (144)][oc16 (16)][lane (32)][4 regs], tf32-rounded.
// reg order matches ldmatrix.x4: j0=(r,c) j1=(r+8,c) j2=(r,c+4) j3=(r+8,c+4),
// r=lane>>2, c=lane&3, within (oc16*16, kb*8) tile of W[256][1152].
__device__ float g_prep[144 * 16 * 32 * 4];

__global__ void __launch_bounds__(256)
prep_weights(const float* __restrict__ w) {
    int idx  = blockIdx.x * 256 + threadIdx.x;     // 0..294911
    int j    = idx & 3;
    int lane = (idx >> 2) & 31;
    int oc16 = (idx >> 7) & 15;
    int kb   = idx >> 11;                          // 0..143
    int row  = oc16 * 16 + (lane >> 2) + ((j & 1) ? 8 : 0);
    int col  = kb * 8 + (lane & 3) + ((j & 2) ? 4 : 0);
    g_prep[idx] = __uint_as_float(totf(w[(size_t)row * 1152 + col]));
}

__global__ void __launch_bounds__(256, 2)
conv3x3_tf32_hmma2(const float* __restrict__ x, float* __restrict__ out)
{
    __shared__ int   s_tbl[1152];
    __shared__ float s_B[2][64 * 20];     // 2 x 64 rows x 80B

    const int tid  = threadIdx.x;
    const int lane = tid & 31;
    const int wid  = tid >> 5;
    const int warpM = wid & 3;            // 0..3 -> 64 oc each
    const int warpN = wid >> 2;           // 0..1 -> 32 px each

    const int gp0 = blockIdx.x << 6;      // 64 flat pixels per CTA

    // ---- k -> (plane offset, r9) table ----
    for (int k = tid; k < 1152; k += 256) {
        int ic = k / 9;
        int r9 = k - ic * 9;
        int kh = r9 / 3;
        int kw = r9 - kh * 3;
        s_tbl[k] = (((ic * 3136) + (kh - 1) * 56 + (kw - 1)) << 4) | r9;
    }

    // ---- per-thread B staging geometry: warp = 32 consecutive px, one k-quad ----
    const int pl   = ((wid & 1) << 5) + lane;   // pixel row in B tile 0..63
    const int quad = wid >> 1;                  // k-quad 0..3 within k16 chunk
    const int gp   = gp0 + pl;
    const int img  = gp / 3136;
    const int p    = gp - img * 3136;
    const int r    = p / 56;
    const int c    = p - r * 56;
    unsigned mask9 = 0;
    #pragma unroll
    for (int dh = -1; dh <= 1; dh++)
        #pragma unroll
        for (int dw = -1; dw <= 1; dw++)
            if ((unsigned)(r + dh) < 56u && (unsigned)(c + dw) < 56u)
                mask9 |= 1u << ((dh + 1) * 3 + (dw + 1));
    const float* pbase = x + (size_t)img * 401408 + p;

    const uint32_t bS = smem_u32(s_B[0]);
    const uint32_t sts_off = (uint32_t)pl * ROWB + (uint32_t)(quad << 4);

    // ldmatrix per-lane base: rows warpN*32 + n-window, k-half windows of 16B
    const uint32_t boff = (uint32_t)((warpN << 5) + (lane & 7) + ((lane >> 4) << 3)) * ROWB
                        + (uint32_t)(((lane >> 3) & 1) << 4);

    // A fragment gmem base for this warp (oc16 tiles warpM*4 .. +3)
    const float4* aP = reinterpret_cast<const float4*>(g_prep) + (size_t)(warpM * 4) * 32 + lane;

    float acc[4][4][4];
    #pragma unroll
    for (int i = 0; i < 4; i++)
        #pragma unroll
        for (int j = 0; j < 4; j++)
            #pragma unroll
            for (int q = 0; q < 4; q++) acc[i][j][q] = 0.0f;

    __syncthreads();   // table ready

    // ---- prologue: stage chunk 0 into buffer 0 ----
    {
        int4 e = *reinterpret_cast<const int4*>(&s_tbl[quad << 2]);
        int ee[4] = {e.x, e.y, e.z, e.w};
        float bv[4];
        #pragma unroll
        for (int j = 0; j < 4; j++) {
            int en = ee[j];
            bool ok = (mask9 >> (en & 15)) & 1u;
            float v = 0.0f;
            if (ok) v = __ldg(pbase + (en >> 4));
            bv[j] = v;
        }
        STS4(bS + sts_off, totf(bv[0]), totf(bv[1]), totf(bv[2]), totf(bv[3]));
    }
    __syncthreads();

    for (int ch = 0; ch < 72; ch++) {
        const int cur = ch & 1;

        // ---- prefetch next chunk's B into regs ----
        float bv[4];
        if (ch < 71) {
            int4 e = *reinterpret_cast<const int4*>(&s_tbl[(ch + 1) * 16 + (quad << 2)]);
            int ee[4] = {e.x, e.y, e.z, e.w};
            #pragma unroll
            for (int j = 0; j < 4; j++) {
                int en = ee[j];
                bool ok = (mask9 >> (en & 15)) & 1u;
                float v = 0.0f;
                if (ok) v = __ldg(pbase + (en >> 4));
                bv[j] = v;
            }
        }

        // ---- compute on current buffer: 2 k8 steps ----
        const uint32_t bBuf = bS + (uint32_t)cur * BTILE;
        #pragma unroll
        for (int s = 0; s < 2; s++) {
            const int kb = ch * 2 + s;
            uint32_t af[4][4];
            #pragma unroll
            for (int i = 0; i < 4; i++) {
                float4 av = __ldg(aP + ((size_t)kb * 16 + i) * 32);
                af[i][0] = __float_as_uint(av.x);
                af[i][1] = __float_as_uint(av.y);
                af[i][2] = __float_as_uint(av.z);
                af[i][3] = __float_as_uint(av.w);
            }
            uint32_t bf[2][4];
            #pragma unroll
            for (int jj = 0; jj < 2; jj++)
                LDSM4(bf[jj], bBuf + boff + (uint32_t)(jj * 16) * ROWB + (uint32_t)(s * 32));
            #pragma unroll
            for (int i = 0; i < 4; i++)
                #pragma unroll
                for (int j = 0; j < 4; j++)
                    MMA1688(acc[i][j], af[i], bf[j >> 1][(j & 1) * 2], bf[j >> 1][(j & 1) * 2 + 1]);
        }

        // ---- store staged regs into the other buffer ----
        if (ch < 71) {
            STS4(bS + (uint32_t)(cur ^ 1) * BTILE + sts_off,
                 totf(bv[0]), totf(bv[1]), totf(bv[2]), totf(bv[3]));
        }
        __syncthreads();
    }

    // ---- epilogue: direct STG.64 per fragment pair ----
    #pragma unroll
    for (int i = 0; i < 4; i++) {
        const int mrow = warpM * 64 + i * 16 + (lane >> 2);
        #pragma unroll
        for (int j = 0; j < 4; j++) {
            int nl  = warpN * 32 + j * 8 + 2 * (lane & 3);
            int gp2 = gp0 + nl;
            int im2 = gp2 / 3136;
            int pp  = gp2 - im2 * 3136;
            float* o0 = out + ((size_t)im2 * 256 + mrow) * 3136 + pp;
            *reinterpret_cast<float2*>(o0)            = make_float2(acc[i][j][0], acc[i][j][1]);
            *reinterpret_cast<float2*>(o0 + 8 * 3136) = make_float2(acc[i][j][2], acc[i][j][3]);
        }
    }
}

extern "C" void kernel_launch(void* const* d_in, const int* in_sizes, int n_in,
                              void* d_out, int out_size) {
    const float* x = (const float*)d_in[0];   // [32,128,56,56]
    const float* w = (const float*)d_in[1];   // [256,128,3,3]
    float* out = (float*)d_out;               // [32,256,56,56]

    prep_weights<<<1152, 256>>>(w);           // 294912 elems, fragment-packed tf32
    conv3x3_tf32_hmma2<<<1568, 256>>>(x, out);
}

// round 6
// speedup vs baseline: 4.4870x; 1.1841x over previous
#include <cuda_runtime.h>
#include <cstdint>

// Conv2d 3x3: x[32,128,56,56] f32 * w[256,128,3,3] f32 -> out[32,256,56,56]
// tf32 mma.sync implicit GEMM. CTA: M=256 oc x N=64 flat px, K=1152 (72 k16 chunks).
// A: fragment-packed tf32 in gmem (prep kernel), LDG.128 + register ping-pong prefetch.
// B: x pre-rounded to tf32 (prep kernel), im2col staged via cp.async zfill, 4-stage ring.

static __device__ __forceinline__ uint32_t smem_u32(const void* p) {
    uint32_t a;
    asm("{ .reg .u64 t; cvta.to.shared.u64 t, %1; cvt.u32.u64 %0, t; }" : "=r"(a) : "l"(p));
    return a;
}
static __device__ __forceinline__ uint32_t totf(float f) {
    float r; asm("cvt.rna.tf32.f32 %0, %1;" : "=f"(r) : "f"(f));
    return __float_as_uint(r);
}

#define LDSM4(r, addr) \
    asm volatile("ldmatrix.sync.aligned.m8n8.x4.shared.b16 {%0,%1,%2,%3}, [%4];" \
        : "=r"((r)[0]), "=r"((r)[1]), "=r"((r)[2]), "=r"((r)[3]) : "r"(addr))

#define MMA1688(d, a, b0, b1) \
    asm volatile("mma.sync.aligned.m16n8k8.row.col.f32.tf32.tf32.f32 " \
        "{%0,%1,%2,%3}, {%4,%5,%6,%7}, {%8,%9}, {%0,%1,%2,%3};" \
        : "+f"((d)[0]), "+f"((d)[1]), "+f"((d)[2]), "+f"((d)[3]) \
        : "r"((a)[0]), "r"((a)[1]), "r"((a)[2]), "r"((a)[3]), "r"(b0), "r"(b1))

static __device__ __forceinline__ void cpa4(uint32_t dst, const float* src, int ok) {
    asm volatile(
        "{\n\t.reg .pred p;\n\t.reg .b32 sz;\n\t"
        "setp.ne.b32 p, %2, 0;\n\t"
        "selp.b32 sz, 4, 0, p;\n\t"
        "cp.async.ca.shared.global [%0], [%1], 4, sz;\n\t}"
        :: "r"(dst), "l"(src), "r"(ok) : "memory");
}
#define CP_COMMIT() asm volatile("cp.async.commit_group;" ::: "memory")
#define CP_WAIT2()  asm volatile("cp.async.wait_group 2;"  ::: "memory")

#define ROWB 80u              // B smem row stride (16 k * 4B + pad)
#define BTILE (64u * ROWB)    // 5120 B per stage
#define NSTAGE 4

// A fragments: [kb(144)][oc16(16)][lane(32)][4], tf32 bits, ldmatrix.x4 reg order.
__device__ float g_prep[144 * 16 * 32 * 4];
// x pre-rounded to tf32 bits (zero-mean rounding preserved through cp.async).
__device__ float g_xtf[32 * 128 * 56 * 56];

__global__ void __launch_bounds__(256)
prep_weights(const float* __restrict__ w) {
    int idx  = blockIdx.x * 256 + threadIdx.x;     // 0..294911
    int j    = idx & 3;
    int lane = (idx >> 2) & 31;
    int oc16 = (idx >> 7) & 15;
    int kb   = idx >> 11;
    int row  = oc16 * 16 + (lane >> 2) + ((j & 1) ? 8 : 0);
    int col  = kb * 8 + (lane & 3) + ((j & 2) ? 4 : 0);
    g_prep[idx] = __uint_as_float(totf(w[(size_t)row * 1152 + col]));
}

__global__ void __launch_bounds__(256)
prep_x(const float* __restrict__ x) {
    size_t i = ((size_t)blockIdx.x * 256 + threadIdx.x) * 4;   // 12845056 / 4 elems
    float4 v = *reinterpret_cast<const float4*>(x + i);
    float4 o;
    o.x = __uint_as_float(totf(v.x));
    o.y = __uint_as_float(totf(v.y));
    o.z = __uint_as_float(totf(v.z));
    o.w = __uint_as_float(totf(v.w));
    *reinterpret_cast<float4*>(g_xtf + i) = o;
}

__global__ void __launch_bounds__(256, 2)
conv3x3_tf32_hmma3(float* __restrict__ out)
{
    __shared__ int   s_tbl[1152];
    __shared__ float s_B[NSTAGE][64 * 20];

    const int tid  = threadIdx.x;
    const int lane = tid & 31;
    const int wid  = tid >> 5;
    const int warpM = wid & 3;            // 64 oc each
    const int warpN = wid >> 2;           // 32 px each

    const int gp0 = blockIdx.x << 6;

    for (int k = tid; k < 1152; k += 256) {
        int ic = k / 9;
        int r9 = k - ic * 9;
        int kh = r9 / 3;
        int kw = r9 - kh * 3;
        s_tbl[k] = (((ic * 3136) + (kh - 1) * 56 + (kw - 1)) << 4) | r9;
    }

    // ---- B staging geometry: warp = 32 consecutive px, one k-quad ----
    const int pl   = ((wid & 1) << 5) + lane;
    const int quad = wid >> 1;
    const int gp   = gp0 + pl;
    const int img  = gp / 3136;
    const int p    = gp - img * 3136;
    const int r    = p / 56;
    const int c    = p - r * 56;
    unsigned mask9 = 0;
    #pragma unroll
    for (int dh = -1; dh <= 1; dh++)
        #pragma unroll
        for (int dw = -1; dw <= 1; dw++)
            if ((unsigned)(r + dh) < 56u && (unsigned)(c + dw) < 56u)
                mask9 |= 1u << ((dh + 1) * 3 + (dw + 1));
    const float* pbase = g_xtf + (size_t)img * 401408 + p;

    const uint32_t bS = smem_u32(s_B[0]);
    const uint32_t sts_off = (uint32_t)pl * ROWB + (uint32_t)(quad << 4);
    const uint32_t boff = (uint32_t)((warpN << 5) + (lane & 7) + ((lane >> 4) << 3)) * ROWB
                        + (uint32_t)(((lane >> 3) & 1) << 4);

    const float4* aP = reinterpret_cast<const float4*>(g_prep) + (size_t)(warpM * 4) * 32 + lane;

    float acc[4][4][4];
    #pragma unroll
    for (int i = 0; i < 4; i++)
        #pragma unroll
        for (int j = 0; j < 4; j++)
            #pragma unroll
            for (int q = 0; q < 4; q++) acc[i][j][q] = 0.0f;

    __syncthreads();   // table ready

    // ---- prologue: stage chunks 0..2 ----
    #pragma unroll
    for (int pre = 0; pre < 3; pre++) {
        int4 e = *reinterpret_cast<const int4*>(&s_tbl[pre * 16 + (quad << 2)]);
        uint32_t d = bS + (uint32_t)pre * BTILE + sts_off;
        int ee[4] = {e.x, e.y, e.z, e.w};
        #pragma unroll
        for (int j = 0; j < 4; j++) {
            int ok = (mask9 >> (ee[j] & 15)) & 1;
            cpa4(d + 4u * j, pbase + (ok ? (ee[j] >> 4) : 0), ok);
        }
        CP_COMMIT();
    }

    // ---- prologue: A regs for kb=0 ----
    uint32_t af[2][4][4];
    #pragma unroll
    for (int i = 0; i < 4; i++) {
        float4 av = __ldg(aP + (size_t)i * 32);
        af[0][i][0] = __float_as_uint(av.x); af[0][i][1] = __float_as_uint(av.y);
        af[0][i][2] = __float_as_uint(av.z); af[0][i][3] = __float_as_uint(av.w);
    }

    for (int ch = 0; ch < 72; ch++) {
        const uint32_t bBuf = bS + (uint32_t)(ch & 3) * BTILE;
        CP_WAIT2();
        __syncthreads();

        // ---- stage chunk ch+3 ----
        if (ch + 3 < 72) {
            int4 e = *reinterpret_cast<const int4*>(&s_tbl[(ch + 3) * 16 + (quad << 2)]);
            uint32_t d = bS + (uint32_t)((ch + 3) & 3) * BTILE + sts_off;
            int ee[4] = {e.x, e.y, e.z, e.w};
            #pragma unroll
            for (int j = 0; j < 4; j++) {
                int ok = (mask9 >> (ee[j] & 15)) & 1;
                cpa4(d + 4u * j, pbase + (ok ? (ee[j] >> 4) : 0), ok);
            }
        }
        CP_COMMIT();

        // ---- compute: 2 k8 steps, A ping-pong prefetch ----
        #pragma unroll
        for (int s = 0; s < 2; s++) {
            const int kb = ch * 2 + s;
            if (kb + 1 < 144) {
                #pragma unroll
                for (int i = 0; i < 4; i++) {
                    float4 av = __ldg(aP + ((size_t)(kb + 1) * 16 + i) * 32);
                    af[s ^ 1][i][0] = __float_as_uint(av.x);
                    af[s ^ 1][i][1] = __float_as_uint(av.y);
                    af[s ^ 1][i][2] = __float_as_uint(av.z);
                    af[s ^ 1][i][3] = __float_as_uint(av.w);
                }
            }
            uint32_t bf[2][4];
            #pragma unroll
            for (int jj = 0; jj < 2; jj++)
                LDSM4(bf[jj], bBuf + boff + (uint32_t)(jj * 16) * ROWB + (uint32_t)(s * 32));
            #pragma unroll
            for (int i = 0; i < 4; i++)
                #pragma unroll
                for (int j = 0; j < 4; j++)
                    MMA1688(acc[i][j], af[s][i], bf[j >> 1][(j & 1) * 2], bf[j >> 1][(j & 1) * 2 + 1]);
        }
    }

    // ---- epilogue ----
    #pragma unroll
    for (int i = 0; i < 4; i++) {
        const int mrow = warpM * 64 + i * 16 + (lane >> 2);
        #pragma unroll
        for (int j = 0; j < 4; j++) {
            int nl  = warpN * 32 + j * 8 + 2 * (lane & 3);
            int gp2 = gp0 + nl;
            int im2 = gp2 / 3136;
            int pp  = gp2 - im2 * 3136;
            float* o0 = out + ((size_t)im2 * 256 + mrow) * 3136 + pp;
            *reinterpret_cast<float2*>(o0)            = make_float2(acc[i][j][0], acc[i][j][1]);
            *reinterpret_cast<float2*>(o0 + 8 * 3136) = make_float2(acc[i][j][2], acc[i][j][3]);
        }
    }
}

extern "C" void kernel_launch(void* const* d_in, const int* in_sizes, int n_in,
                              void* d_out, int out_size) {
    const float* x = (const float*)d_in[0];   // [32,128,56,56]
    const float* w = (const float*)d_in[1];   // [256,128,3,3]
    float* out = (float*)d_out;               // [32,256,56,56]

    prep_weights<<<1152, 256>>>(w);
    prep_x<<<12544, 256>>>(x);                // 12845056 elems / 4 per thread
    conv3x3_tf32_hmma3<<<1568, 256>>>(out);
}